// round 3
// baseline (speedup 1.0000x reference)
#include <cuda_runtime.h>
#include <math.h>
#include <stdint.h>

// Problem shapes (fixed by the dataset)
constexpr int Bb = 16;    // batch
constexpr int Ss = 2048;  // tokens
constexpr int Dd = 512;   // dim
constexpr int Mm = 256;   // memory slots
constexpr int Rr = 64;    // low rank
constexpr float EPS = 1e-5f;
constexpr float STATE_MASS = 4.0f;
constexpr float LRS = 0.1f;

// ---------------- scratch (static device globals; no allocs) ----------------
__device__ float g_ps[(size_t)Bb * Ss * Rr];       // 8.4 MB   [b*S+s][r]
__device__ float g_mem_val0[(size_t)Mm * Dd];      // LN(init_val), batch-independent
__device__ float g_pt2[(size_t)Mm * Rr];           // (mem_val0@rUt + b) * r_w * 0.1
__device__ float g_mem_state0[Mm];                 // signed-softmax-state(init_state)
__device__ float g_mem_val1[(size_t)Bb * Mm * Dd]; // post-write, post-LN
__device__ float g_state1_raw[(size_t)Bb * Mm];
__device__ float g_state1[(size_t)Bb * Mm];
__device__ float g_qt[(size_t)Bb * Mm * Rr];       // (mem_val1@pUt + b) * p_w * 0.1
__device__ float g_qs2[(size_t)Bb * Mm * Rr];      // (mem_val1@pUs + b) * state1[b,j]
__device__ float g_edge[(size_t)Bb * Mm * 16];     // selected edge weights
__device__ int   g_eidx[(size_t)Bb * Mm * 16];     // selected token indices

// ---------------- shared helpers ----------------
__device__ __forceinline__ void block_ln_512(float a0, float a1, float& mu, float& ri,
                                             float* swr) {
    float ps = a0 + a1;
    float pq = fmaf(a0, a0, a1 * a1);
#pragma unroll
    for (int off = 16; off; off >>= 1) {
        ps += __shfl_down_sync(0xffffffffu, ps, off);
        pq += __shfl_down_sync(0xffffffffu, pq, off);
    }
    int tid = threadIdx.x, wid = tid >> 5, lane = tid & 31;
    if (lane == 0) { swr[wid] = ps; swr[8 + wid] = pq; }
    __syncthreads();
    if (tid == 0) {
        float s = 0.f, q = 0.f;
#pragma unroll
        for (int i = 0; i < 8; i++) { s += swr[i]; q += swr[8 + i]; }
        float m = s * (1.0f / 512.0f);
        float v = q * (1.0f / 512.0f) - m * m;
        swr[16] = m;
        swr[17] = rsqrtf(v + EPS);
    }
    __syncthreads();
    mu = swr[16];
    ri = swr[17];
}

// ---------------- kernel: LayerNorm rows (row length 512) ----------------
__global__ void ln_rows_kernel(const float* __restrict__ in, float* __restrict__ out,
                               const float* __restrict__ g, const float* __restrict__ bta) {
    __shared__ float swr[18];
    int row = blockIdx.x, tid = threadIdx.x;
    const float* x = in + (size_t)row * Dd;
    float a0 = x[tid], a1 = x[tid + 256];
    float mu, ri;
    block_ln_512(a0, a1, mu, ri, swr);
    float* o = out + (size_t)row * Dd;
    o[tid]       = (a0 - mu) * ri * g[tid] + bta[tid];
    o[tid + 256] = (a1 - mu) * ri * g[tid + 256] + bta[tid + 256];
}

// ---------------- kernel: signed softmax state over 256 slots ----------------
__global__ void sss_kernel(const float* __restrict__ in, float* __restrict__ out) {
    int tid = threadIdx.x;
    const float* x = in + (size_t)blockIdx.x * Mm;
    float v = x[tid];
    float a = fabsf(v);
    __shared__ float swr[8];
    __shared__ float s_bc[2];
    int wid = tid >> 5, lane = tid & 31;
    float m = a;
#pragma unroll
    for (int off = 16; off; off >>= 1) m = fmaxf(m, __shfl_down_sync(0xffffffffu, m, off));
    if (lane == 0) swr[wid] = m;
    __syncthreads();
    if (tid == 0) {
        float mm = swr[0];
#pragma unroll
        for (int i = 1; i < 8; i++) mm = fmaxf(mm, swr[i]);
        s_bc[0] = mm;
    }
    __syncthreads();
    float e = expf(a - s_bc[0]);
    float s = e;
#pragma unroll
    for (int off = 16; off; off >>= 1) s += __shfl_down_sync(0xffffffffu, s, off);
    __syncthreads();
    if (lane == 0) swr[wid] = s;
    __syncthreads();
    if (tid == 0) {
        float ss = 0.f;
#pragma unroll
        for (int i = 0; i < 8; i++) ss += swr[i];
        s_bc[1] = ss;
    }
    __syncthreads();
    float sgn = (v > 0.f) ? 1.f : ((v < 0.f) ? -1.f : 0.f);
    out[(size_t)blockIdx.x * Mm + tid] = sgn * e / s_bc[1] * STATE_MASS;
}

// ---------------- tiled projection GEMM: out[rows,64] = X[rows,512] @ W[512,64] ----------------
template <int RT>
__global__ __launch_bounds__(256) void gemm_proj(
    const float* __restrict__ X,
    float* __restrict__ out0, const float* __restrict__ W0, const float* __restrict__ b0,
    const float* __restrict__ rs0, const float* __restrict__ rowsc0,
    float* __restrict__ out1, const float* __restrict__ W1, const float* __restrict__ b1,
    const float* __restrict__ rs1, const float* __restrict__ rowsc1) {
    constexpr int RPT = RT / 16;       // rows per thread
    constexpr int XSTR = RT + 4;       // padded smem stride (floats)
    __shared__ float sx[16 * XSTR];
    __shared__ float sw[16 * 68];

    int tid = threadIdx.x;
    int row0 = blockIdx.x * RT;
    int set = blockIdx.y;
    const float* W     = set ? W1 : W0;
    const float* bias  = set ? b1 : b0;
    const float* rs    = set ? rs1 : rs0;
    const float* rowsc = set ? rowsc1 : rowsc0;
    float* out         = set ? out1 : out0;

    int rowg = tid >> 4;       // 16 row groups
    int colg = tid & 15;       // 16 col groups x 4 cols

    float acc[RPT][4];
#pragma unroll
    for (int r = 0; r < RPT; r++)
#pragma unroll
        for (int c = 0; c < 4; c++) acc[r][c] = 0.f;

    for (int k0 = 0; k0 < Dd; k0 += 16) {
        constexpr int NV = RT * 16 / 4;  // float4 count
#pragma unroll
        for (int t = 0; t < (NV + 255) / 256; t++) {
            int f = tid + 256 * t;
            if ((NV % 256 == 0) || (f < NV)) {
                int row = f >> 2, q = f & 3;
                float4 v = *(const float4*)&X[(size_t)(row0 + row) * Dd + k0 + 4 * q];
                sx[(4 * q + 0) * XSTR + row] = v.x;
                sx[(4 * q + 1) * XSTR + row] = v.y;
                sx[(4 * q + 2) * XSTR + row] = v.z;
                sx[(4 * q + 3) * XSTR + row] = v.w;
            }
        }
        {
            int k = tid >> 4, c = tid & 15;
            float4 v = *(const float4*)&W[(size_t)(k0 + k) * Rr + 4 * c];
            *(float4*)&sw[k * 68 + 4 * c] = v;
        }
        __syncthreads();
#pragma unroll
        for (int kk = 0; kk < 16; kk++) {
            float4 wv = *(const float4*)&sw[kk * 68 + colg * 4];
            float xr[RPT];
            if constexpr (RPT == 8) {
                float4 x0 = *(const float4*)&sx[kk * XSTR + rowg * 8];
                float4 x1 = *(const float4*)&sx[kk * XSTR + rowg * 8 + 4];
                xr[0] = x0.x; xr[1] = x0.y; xr[2] = x0.z; xr[3] = x0.w;
                xr[4] = x1.x; xr[5] = x1.y; xr[6] = x1.z; xr[7] = x1.w;
            } else {
                float2 x0 = *(const float2*)&sx[kk * XSTR + rowg * RPT];
                xr[0] = x0.x; xr[1] = x0.y;
            }
#pragma unroll
            for (int r = 0; r < RPT; r++) {
                acc[r][0] = fmaf(xr[r], wv.x, acc[r][0]);
                acc[r][1] = fmaf(xr[r], wv.y, acc[r][1]);
                acc[r][2] = fmaf(xr[r], wv.z, acc[r][2]);
                acc[r][3] = fmaf(xr[r], wv.w, acc[r][3]);
            }
        }
        __syncthreads();
    }

    float4 bv = *(const float4*)&bias[colg * 4];
    float s0 = 1.f, s1 = 1.f, s2 = 1.f, s3 = 1.f;
    if (rs) {
        float4 rv = *(const float4*)&rs[colg * 4];
        s0 = rv.x * LRS; s1 = rv.y * LRS; s2 = rv.z * LRS; s3 = rv.w * LRS;
    }
#pragma unroll
    for (int r = 0; r < RPT; r++) {
        int row = row0 + rowg * RPT + r;
        float rsc = rowsc ? rowsc[row] : 1.f;
        float4 o;
        o.x = (acc[r][0] + bv.x) * s0 * rsc;
        o.y = (acc[r][1] + bv.y) * s1 * rsc;
        o.z = (acc[r][2] + bv.z) * s2 * rsc;
        o.w = (acc[r][3] + bv.w) * s3 * rsc;
        *(float4*)&out[(size_t)row * Rr + colg * 4] = o;
    }
}

// ---------------- fused scores GEMM + streaming top-16 + edges ----------------
// grid (M/32, B), 256 threads (8 warps). Warp w owns m-rows 4w..4w+3 of the tile.
// Streams s in chunks of 64; maintains per-row top-16 (ascending-index streaming,
// strict >, evict largest-index-among-min => identical set to jax.lax.top_k).
__device__ __forceinline__ void topk_insert(float (*lval)[16], int (*lidx)[16],
                                            float* lthr, int row, float v, int s) {
    float av = fabsf(v);
    if (av > lthr[row]) {   // uniform across warp
        int jb = 0; float bmin = 1e30f; int bid = -1;
#pragma unroll
        for (int j = 0; j < 16; j++) {
            float a = fabsf(lval[row][j]); int id = lidx[row][j];
            if (a < bmin || (a == bmin && id > bid)) { bmin = a; bid = id; jb = j; }
        }
        lval[row][jb] = v; lidx[row][jb] = s;
        float nm = 1e30f;
#pragma unroll
        for (int j = 0; j < 16; j++) nm = fminf(nm, fabsf(lval[row][j]));
        lthr[row] = nm;
    }
}

__global__ __launch_bounds__(256) void scores_topk_kernel(
    const float* __restrict__ token_state) {
    __shared__ float sps[64][68];   // ps chunk [s][r]
    __shared__ float spt[32][68];   // pt2 tile [m][r]
    __shared__ float ssc[32][68];   // scores chunk [m][s]
    __shared__ float lval[32][16];  // top-16 signed values
    __shared__ int   lidx[32][16];  // top-16 indices
    __shared__ float lthr[32];      // current 16th |value|

    int tid = threadIdx.x, w = tid >> 5, lane = tid & 31;
    int m0 = blockIdx.x * 32;
    int b = blockIdx.y;

    // stage pt2 tile once
#pragma unroll
    for (int t = 0; t < 2; t++) {
        int f = tid + 256 * t;
        int m = f >> 4, q = f & 15;
        *(float4*)&spt[m][q * 4] = *(const float4*)&g_pt2[(size_t)(m0 + m) * Rr + 4 * q];
    }

    const float* psb = g_ps + (size_t)b * Ss * Rr;
    int sg = tid & 31, mg = tid >> 5;  // mg == w

    for (int sc0 = 0; sc0 < Ss; sc0 += 64) {
        // stage ps chunk [64 s][64 r]
#pragma unroll
        for (int t = 0; t < 4; t++) {
            int f = tid + 256 * t;
            int s = f >> 4, q = f & 15;
            *(float4*)&sps[s][q * 4] = *(const float4*)&psb[(size_t)(sc0 + s) * Rr + 4 * q];
        }
        __syncthreads();  // also protects ssc from previous chunk's scan

        // GEMM: 32m x 64s; thread = 4m x 2s (s = sg, sg+32)
        float acc[4][2];
#pragma unroll
        for (int i = 0; i < 4; i++) { acc[i][0] = 0.f; acc[i][1] = 0.f; }
#pragma unroll
        for (int r4 = 0; r4 < Rr; r4 += 4) {
            float4 q0 = *(const float4*)&sps[sg][r4];
            float4 q1 = *(const float4*)&sps[sg + 32][r4];
#pragma unroll
            for (int i = 0; i < 4; i++) {
                float4 p = *(const float4*)&spt[mg * 4 + i][r4];
                acc[i][0] = fmaf(p.x, q0.x, fmaf(p.y, q0.y, fmaf(p.z, q0.z, fmaf(p.w, q0.w, acc[i][0]))));
                acc[i][1] = fmaf(p.x, q1.x, fmaf(p.y, q1.y, fmaf(p.z, q1.z, fmaf(p.w, q1.w, acc[i][1]))));
            }
        }
#pragma unroll
        for (int i = 0; i < 4; i++) {
            ssc[mg * 4 + i][sg]      = acc[i][0];
            ssc[mg * 4 + i][sg + 32] = acc[i][1];
        }
        __syncthreads();

        // streaming top-16 scan (warp-private rows; no cross-warp sync needed)
#pragma unroll
        for (int i = 0; i < 4; i++) {
            int row = 4 * w + i;
            float v0 = ssc[row][lane];        // s_local = lane
            float v1 = ssc[row][lane + 32];   // s_local = lane + 32
            if (sc0 == 0) {
                if (lane < 16) { lval[row][lane] = v0; lidx[row][lane] = lane; }
                __syncwarp();
                float nm = 1e30f;
#pragma unroll
                for (int j = 0; j < 16; j++) nm = fminf(nm, fabsf(lval[row][j]));
                lthr[row] = nm;
                __syncwarp();
            }
            float thr = lthr[row];  // stale threshold => superset ballot; re-check inside
            bool e0 = (sc0 > 0) || (lane >= 16);
            unsigned bal0 = __ballot_sync(0xffffffffu, e0 && (fabsf(v0) > thr));
            unsigned bal1 = __ballot_sync(0xffffffffu, fabsf(v1) > thr);
            while (bal0) {
                int l = __ffs(bal0) - 1; bal0 &= bal0 - 1;
                float v = __shfl_sync(0xffffffffu, v0, l);
                topk_insert(lval, lidx, lthr, row, v, sc0 + l);
            }
            while (bal1) {
                int l = __ffs(bal1) - 1; bal1 &= bal1 - 1;
                float v = __shfl_sync(0xffffffffu, v1, l);
                topk_insert(lval, lidx, lthr, row, v, sc0 + 32 + l);
            }
        }
    }
    __syncthreads();

    // finalize: signed-abs-softmax edges + state update (per row, lanes 0..15)
#pragma unroll
    for (int i = 0; i < 4; i++) {
        int row = 4 * w + i;
        int mglob = m0 + row;
        int bm = b * Mm + mglob;
        bool valid = lane < 16;
        float v = valid ? lval[row][lane] : 0.f;
        int idx = valid ? lidx[row][lane] : 0;
        float a = valid ? fabsf(v) : -1e30f;
        float mx = a;
#pragma unroll
        for (int off = 8; off; off >>= 1) mx = fmaxf(mx, __shfl_xor_sync(0xffffffffu, mx, off, 16));
        float e = valid ? expf(a - mx) : 0.f;
        float sm = e;
#pragma unroll
        for (int off = 8; off; off >>= 1) sm += __shfl_xor_sync(0xffffffffu, sm, off, 16);
        float sgn = (v > 0.f) ? 1.f : ((v < 0.f) ? -1.f : 0.f);
        float edge = sgn * e / sm;
        if (valid) {
            g_edge[(size_t)bm * 16 + lane] = edge;
            g_eidx[(size_t)bm * 16 + lane] = idx;
        }
        float c = valid ? edge * token_state[(size_t)b * Ss + idx] : 0.f;
#pragma unroll
        for (int off = 8; off; off >>= 1) c += __shfl_xor_sync(0xffffffffu, c, off, 16);
        if (lane == 0) g_state1_raw[bm] = g_mem_state0[mglob] + c;
    }
}

// ---------------- kernel: apply write edges (gather-add + LN) ----------------
__global__ __launch_bounds__(256) void apply_kernel(
    const float* __restrict__ token_val,
    const float* __restrict__ ln_g, const float* __restrict__ ln_b) {
    int bm = blockIdx.x;
    int b = bm >> 8, m = bm & 255;
    int tid = threadIdx.x;
    __shared__ float s_edge[16];
    __shared__ int s_eidx[16];
    __shared__ float swr[18];
    if (tid < 16) {
        s_edge[tid] = g_edge[(size_t)bm * 16 + tid];
        s_eidx[tid] = g_eidx[(size_t)bm * 16 + tid];
    }
    __syncthreads();

    int d = tid;
    float a0 = g_mem_val0[(size_t)m * Dd + d];
    float a1 = g_mem_val0[(size_t)m * Dd + d + 256];
#pragma unroll
    for (int k = 0; k < 16; k++) {
        const float* tv = token_val + ((size_t)b * Ss + s_eidx[k]) * Dd;
        float ek = s_edge[k];
        a0 = fmaf(ek, tv[d], a0);
        a1 = fmaf(ek, tv[d + 256], a1);
    }
    float mu, ri;
    block_ln_512(a0, a1, mu, ri, swr);
    float* o = g_mem_val1 + (size_t)bm * Dd;
    o[d]       = (a0 - mu) * ri * ln_g[d] + ln_b[d];
    o[d + 256] = (a1 - mu) * ri * ln_g[d + 256] + ln_b[d + 256];
}

// ---------------- kernel: propagation (pscores row, top-16, residual, final LN) ----------------
__global__ __launch_bounds__(256) void prop_kernel(
    float* __restrict__ out_final, const float* __restrict__ ln_g,
    const float* __restrict__ ln_b) {
    int bi = blockIdx.x;
    int b = bi >> 8;
    int tid = threadIdx.x, w = tid >> 5, lane = tid & 31;
    __shared__ float s_qt[64];
    __shared__ float s_prow[256];
    __shared__ float s_edge[16];
    __shared__ int s_eidx[16];
    __shared__ float swr[18];

    if (tid < 64) s_qt[tid] = g_qt[(size_t)bi * Rr + tid];
    __syncthreads();

    {
        const float* q = g_qs2 + ((size_t)(b * Mm) + tid) * Rr;
        float acc = 0.f;
#pragma unroll
        for (int r = 0; r < Rr; r += 4) {
            float4 qv = *(const float4*)(q + r);
            acc = fmaf(qv.x, s_qt[r], acc);
            acc = fmaf(qv.y, s_qt[r + 1], acc);
            acc = fmaf(qv.z, s_qt[r + 2], acc);
            acc = fmaf(qv.w, s_qt[r + 3], acc);
        }
        s_prow[tid] = acc;
    }
    __syncthreads();

    if (w == 0) {
        float va[8];
#pragma unroll
        for (int j = 0; j < 8; j++) va[j] = fabsf(s_prow[lane + 32 * j]);
        float myabs = 0.f;
        int myidx = 0;
        for (int p = 0; p < 16; p++) {
            float best = -1.f;
            int bj = 0;
#pragma unroll
            for (int j = 0; j < 8; j++)
                if (va[j] > best) { best = va[j]; bj = j; }
            int bidx = lane + 32 * bj;
#pragma unroll
            for (int off = 16; off; off >>= 1) {
                float ob = __shfl_down_sync(0xffffffffu, best, off);
                int oi = __shfl_down_sync(0xffffffffu, bidx, off);
                if (ob > best || (ob == best && oi < bidx)) { best = ob; bidx = oi; }
            }
            best = __shfl_sync(0xffffffffu, best, 0);
            bidx = __shfl_sync(0xffffffffu, bidx, 0);
#pragma unroll
            for (int j = 0; j < 8; j++)
                if (lane + 32 * j == bidx) va[j] = -1.f;
            if (lane == p) { myabs = best; myidx = bidx; }
        }
        float maxa = __shfl_sync(0xffffffffu, myabs, 0);
        bool valid = lane < 16;
        float sel = valid ? s_prow[myidx] : 0.f;
        float e = valid ? expf(myabs - maxa) : 0.f;
        float sum = e;
#pragma unroll
        for (int off = 16; off; off >>= 1) sum += __shfl_xor_sync(0xffffffffu, sum, off);
        float sgn = (sel > 0.f) ? 1.f : ((sel < 0.f) ? -1.f : 0.f);
        float edge = sgn * e / sum;
        if (valid) { s_edge[lane] = edge; s_eidx[lane] = myidx; }
    }
    __syncthreads();

    int d = tid;
    float a0 = g_mem_val1[(size_t)bi * Dd + d];
    float a1 = g_mem_val1[(size_t)bi * Dd + d + 256];
#pragma unroll
    for (int k = 0; k < 16; k++) {
        const float* mv = g_mem_val1 + ((size_t)(b * Mm + s_eidx[k])) * Dd;
        float ek = s_edge[k];
        a0 = fmaf(ek, mv[d], a0);
        a1 = fmaf(ek, mv[d + 256], a1);
    }
    float mu, ri;
    block_ln_512(a0, a1, mu, ri, swr);
    float* o = out_final + (size_t)bi * Dd;
    o[d]       = (a0 - mu) * ri * ln_g[d] + ln_b[d];
    o[d + 256] = (a1 - mu) * ri * ln_g[d + 256] + ln_b[d + 256];
}

// ---------------- host launch ----------------
extern "C" void kernel_launch(void* const* d_in, const int* in_sizes, int n_in,
                              void* d_out, int out_size) {
    (void)in_sizes; (void)n_in; (void)out_size;
    const float* token_val   = (const float*)d_in[0];
    const float* token_state = (const float*)d_in[1];
    const float* init_state  = (const float*)d_in[2];
    const float* init_val    = (const float*)d_in[3];
    const float* rUs_w = (const float*)d_in[4];
    const float* rUs_b = (const float*)d_in[5];
    const float* rUt_w = (const float*)d_in[6];
    const float* rUt_b = (const float*)d_in[7];
    const float* r_w   = (const float*)d_in[8];
    const float* pUs_w = (const float*)d_in[9];
    const float* pUs_b = (const float*)d_in[10];
    const float* pUt_w = (const float*)d_in[11];
    const float* pUt_b = (const float*)d_in[12];
    const float* p_w   = (const float*)d_in[13];
    const float* ln_g  = (const float*)d_in[14];
    const float* ln_b  = (const float*)d_in[15];
    float* out = (float*)d_out;

    float *p_mv0, *p_pt2, *p_ps, *p_mv1, *p_qt, *p_qs2, *p_st0, *p_st1raw, *p_st1;
    cudaGetSymbolAddress((void**)&p_mv0, g_mem_val0);
    cudaGetSymbolAddress((void**)&p_pt2, g_pt2);
    cudaGetSymbolAddress((void**)&p_ps, g_ps);
    cudaGetSymbolAddress((void**)&p_mv1, g_mem_val1);
    cudaGetSymbolAddress((void**)&p_qt, g_qt);
    cudaGetSymbolAddress((void**)&p_qs2, g_qs2);
    cudaGetSymbolAddress((void**)&p_st0, g_mem_state0);
    cudaGetSymbolAddress((void**)&p_st1raw, g_state1_raw);
    cudaGetSymbolAddress((void**)&p_st1, g_state1);

    // mem_val0 = LN(init_val)  (batch independent)
    ln_rows_kernel<<<Mm, 256>>>(init_val, p_mv0, ln_g, ln_b);
    // mem_state0 = signed_softmax_state(init_state)
    sss_kernel<<<1, 256>>>(init_state, p_st0);
    // pt2 = (mem_val0 @ rUt + b) * r_w * 0.1
    gemm_proj<32><<<dim3(Mm / 32, 1), 256>>>(p_mv0,
        p_pt2, rUt_w, rUt_b, r_w, nullptr,
        nullptr, nullptr, nullptr, nullptr, nullptr);
    // ps = token_val @ rUs + b
    gemm_proj<128><<<dim3((Bb * Ss) / 128, 1), 256>>>(token_val,
        p_ps, rUs_w, rUs_b, nullptr, nullptr,
        nullptr, nullptr, nullptr, nullptr, nullptr);
    // fused scores GEMM + top-16 + edges + raw state update
    scores_topk_kernel<<<dim3(Mm / 32, Bb), 256>>>(token_state);
    // gather-add + LN -> mem_val1
    apply_kernel<<<Bb * Mm, 256>>>(token_val, ln_g, ln_b);
    // state1 = signed_softmax_state(state1_raw)
    sss_kernel<<<Bb, 256>>>(p_st1raw, p_st1);
    // fused: y=0 -> qt, y=1 -> qs2 (state folded into rows)
    gemm_proj<32><<<dim3((Bb * Mm) / 32, 2), 256>>>(p_mv1,
        p_qt, pUt_w, pUt_b, p_w, nullptr,
        p_qs2, pUs_w, pUs_b, nullptr, p_st1);
    // propagation + final LN -> out
    prop_kernel<<<Bb * Mm, 256>>>(out, ln_g, ln_b);
}

// round 4
// speedup vs baseline: 1.5940x; 1.5940x over previous
#include <cuda_runtime.h>
#include <math.h>
#include <stdint.h>

// Problem shapes (fixed by the dataset)
constexpr int Bb = 16;    // batch
constexpr int Ss = 2048;  // tokens
constexpr int Dd = 512;   // dim
constexpr int Mm = 256;   // memory slots
constexpr int Rr = 64;    // low rank
constexpr float EPS = 1e-5f;
constexpr float STATE_MASS = 4.0f;
constexpr float LRS = 0.1f;

// ---------------- scratch (static device globals; no allocs) ----------------
__device__ float g_scores[(size_t)Bb * Mm * Ss];   // 33.5 MB (L2-resident) [b][m][s]
__device__ float g_ps[(size_t)Bb * Ss * Rr];       // 8.4 MB   [b*S+s][r]
__device__ float g_mem_val0[(size_t)Mm * Dd];      // LN(init_val), batch-independent
__device__ float g_pt2[(size_t)Mm * Rr];           // (mem_val0@rUt + b) * r_w * 0.1
__device__ float g_mem_state0[Mm];                 // signed-softmax-state(init_state)
__device__ float g_mem_val1[(size_t)Bb * Mm * Dd]; // post-write, post-LN
__device__ float g_state1_raw[(size_t)Bb * Mm];
__device__ float g_state1[(size_t)Bb * Mm];
__device__ float g_qt[(size_t)Bb * Mm * Rr];       // (mem_val1@pUt + b) * p_w * 0.1
__device__ float g_qs2[(size_t)Bb * Mm * Rr];      // (mem_val1@pUs + b) * state1[b,j]

// ---------------- shared helpers ----------------
__device__ __forceinline__ void block_ln_512(float a0, float a1, float& mu, float& ri,
                                             float* swr) {
    float ps = a0 + a1;
    float pq = fmaf(a0, a0, a1 * a1);
#pragma unroll
    for (int off = 16; off; off >>= 1) {
        ps += __shfl_down_sync(0xffffffffu, ps, off);
        pq += __shfl_down_sync(0xffffffffu, pq, off);
    }
    int tid = threadIdx.x, wid = tid >> 5, lane = tid & 31;
    if (lane == 0) { swr[wid] = ps; swr[8 + wid] = pq; }
    __syncthreads();
    if (tid == 0) {
        float s = 0.f, q = 0.f;
#pragma unroll
        for (int i = 0; i < 8; i++) { s += swr[i]; q += swr[8 + i]; }
        float m = s * (1.0f / 512.0f);
        float v = q * (1.0f / 512.0f) - m * m;
        swr[16] = m;
        swr[17] = rsqrtf(v + EPS);
    }
    __syncthreads();
    mu = swr[16];
    ri = swr[17];
}

// ---------------- kernel: LayerNorm rows (row length 512) ----------------
__global__ void ln_rows_kernel(const float* __restrict__ in, float* __restrict__ out,
                               const float* __restrict__ g, const float* __restrict__ bta) {
    __shared__ float swr[18];
    int row = blockIdx.x, tid = threadIdx.x;
    const float* x = in + (size_t)row * Dd;
    float a0 = x[tid], a1 = x[tid + 256];
    float mu, ri;
    block_ln_512(a0, a1, mu, ri, swr);
    float* o = out + (size_t)row * Dd;
    o[tid]       = (a0 - mu) * ri * g[tid] + bta[tid];
    o[tid + 256] = (a1 - mu) * ri * g[tid + 256] + bta[tid + 256];
}

// ---------------- kernel: signed softmax state over 256 slots ----------------
__global__ void sss_kernel(const float* __restrict__ in, float* __restrict__ out) {
    int tid = threadIdx.x;
    const float* x = in + (size_t)blockIdx.x * Mm;
    float v = x[tid];
    float a = fabsf(v);
    __shared__ float swr[8];
    __shared__ float s_bc[2];
    int wid = tid >> 5, lane = tid & 31;
    float m = a;
#pragma unroll
    for (int off = 16; off; off >>= 1) m = fmaxf(m, __shfl_down_sync(0xffffffffu, m, off));
    if (lane == 0) swr[wid] = m;
    __syncthreads();
    if (tid == 0) {
        float mm = swr[0];
#pragma unroll
        for (int i = 1; i < 8; i++) mm = fmaxf(mm, swr[i]);
        s_bc[0] = mm;
    }
    __syncthreads();
    float e = expf(a - s_bc[0]);
    float s = e;
#pragma unroll
    for (int off = 16; off; off >>= 1) s += __shfl_down_sync(0xffffffffu, s, off);
    __syncthreads();
    if (lane == 0) swr[wid] = s;
    __syncthreads();
    if (tid == 0) {
        float ss = 0.f;
#pragma unroll
        for (int i = 0; i < 8; i++) ss += swr[i];
        s_bc[1] = ss;
    }
    __syncthreads();
    float sgn = (v > 0.f) ? 1.f : ((v < 0.f) ? -1.f : 0.f);
    out[(size_t)blockIdx.x * Mm + tid] = sgn * e / s_bc[1] * STATE_MASS;
}

// ---------------- tiled projection GEMM: out[rows,64] = X[rows,512] @ W[512,64] ----------------
// Two parameter sets. If split >= 0: set = (blockIdx.x >= split) (single-y combined launch).
// Else set = blockIdx.y.
template <int RT>
__global__ __launch_bounds__(256) void gemm_proj(
    int split,
    const float* __restrict__ X0,
    float* __restrict__ out0, const float* __restrict__ W0, const float* __restrict__ b0,
    const float* __restrict__ rs0, const float* __restrict__ rowsc0,
    const float* __restrict__ X1,
    float* __restrict__ out1, const float* __restrict__ W1, const float* __restrict__ b1,
    const float* __restrict__ rs1, const float* __restrict__ rowsc1) {
    constexpr int RPT = RT / 16;       // rows per thread
    constexpr int XSTR = RT + 4;       // padded smem stride (floats)
    __shared__ float sx[16 * XSTR];
    __shared__ float sw[16 * 68];

    int tid = threadIdx.x;
    int set, rowblk;
    if (split >= 0) {
        set = ((int)blockIdx.x >= split);
        rowblk = set ? (int)blockIdx.x - split : (int)blockIdx.x;
    } else {
        set = blockIdx.y;
        rowblk = blockIdx.x;
    }
    int row0 = rowblk * RT;
    const float* X     = set ? X1 : X0;
    const float* W     = set ? W1 : W0;
    const float* bias  = set ? b1 : b0;
    const float* rs    = set ? rs1 : rs0;
    const float* rowsc = set ? rowsc1 : rowsc0;
    float* out         = set ? out1 : out0;

    int rowg = tid >> 4;       // 16 row groups
    int colg = tid & 15;       // 16 col groups x 4 cols

    float acc[RPT][4];
#pragma unroll
    for (int r = 0; r < RPT; r++)
#pragma unroll
        for (int c = 0; c < 4; c++) acc[r][c] = 0.f;

    for (int k0 = 0; k0 < Dd; k0 += 16) {
        constexpr int NV = RT * 16 / 4;  // float4 count
#pragma unroll
        for (int t = 0; t < (NV + 255) / 256; t++) {
            int f = tid + 256 * t;
            if ((NV % 256 == 0) || (f < NV)) {
                int row = f >> 2, q = f & 3;
                float4 v = *(const float4*)&X[(size_t)(row0 + row) * Dd + k0 + 4 * q];
                sx[(4 * q + 0) * XSTR + row] = v.x;
                sx[(4 * q + 1) * XSTR + row] = v.y;
                sx[(4 * q + 2) * XSTR + row] = v.z;
                sx[(4 * q + 3) * XSTR + row] = v.w;
            }
        }
        {
            int k = tid >> 4, c = tid & 15;
            float4 v = *(const float4*)&W[(size_t)(k0 + k) * Rr + 4 * c];
            *(float4*)&sw[k * 68 + 4 * c] = v;
        }
        __syncthreads();
#pragma unroll
        for (int kk = 0; kk < 16; kk++) {
            float4 wv = *(const float4*)&sw[kk * 68 + colg * 4];
            float xr[RPT];
            if constexpr (RPT == 8) {
                float4 x0 = *(const float4*)&sx[kk * XSTR + rowg * 8];
                float4 x1 = *(const float4*)&sx[kk * XSTR + rowg * 8 + 4];
                xr[0] = x0.x; xr[1] = x0.y; xr[2] = x0.z; xr[3] = x0.w;
                xr[4] = x1.x; xr[5] = x1.y; xr[6] = x1.z; xr[7] = x1.w;
            } else {
                float2 x0 = *(const float2*)&sx[kk * XSTR + rowg * RPT];
                xr[0] = x0.x; xr[1] = x0.y;
            }
#pragma unroll
            for (int r = 0; r < RPT; r++) {
                acc[r][0] = fmaf(xr[r], wv.x, acc[r][0]);
                acc[r][1] = fmaf(xr[r], wv.y, acc[r][1]);
                acc[r][2] = fmaf(xr[r], wv.z, acc[r][2]);
                acc[r][3] = fmaf(xr[r], wv.w, acc[r][3]);
            }
        }
        __syncthreads();
    }

    float4 bv = *(const float4*)&bias[colg * 4];
    float s0 = 1.f, s1 = 1.f, s2 = 1.f, s3 = 1.f;
    if (rs) {
        float4 rv = *(const float4*)&rs[colg * 4];
        s0 = rv.x * LRS; s1 = rv.y * LRS; s2 = rv.z * LRS; s3 = rv.w * LRS;
    }
#pragma unroll
    for (int r = 0; r < RPT; r++) {
        int row = row0 + rowg * RPT + r;
        float rsc = rowsc ? rowsc[row] : 1.f;
        float4 o;
        o.x = (acc[r][0] + bv.x) * s0 * rsc;
        o.y = (acc[r][1] + bv.y) * s1 * rsc;
        o.z = (acc[r][2] + bv.z) * s2 * rsc;
        o.w = (acc[r][3] + bv.w) * s3 * rsc;
        *(float4*)&out[(size_t)row * Rr + colg * 4] = o;
    }
}

// ---------------- tiled scores GEMM: scores[b][m][s] = sum_r pt2[m][r] * ps[b][s][r] ----------------
// Block tile 128 s x 128 m, r chunks of 16 staged transposed in smem. 8x8 thread tile.
// grid (S/128, M/128, B)
__global__ __launch_bounds__(256) void scores2_kernel() {
    __shared__ float sps[16 * 132];  // [r][s]
    __shared__ float spt[16 * 132];  // [r][m]
    int b = blockIdx.z;
    int s0 = blockIdx.x * 128;
    int m0 = blockIdx.y * 128;
    int tid = threadIdx.x;
    int sg = (tid & 15) * 8;
    int mg = (tid >> 4) * 8;

    const float* psg = g_ps + ((size_t)b * Ss + s0) * Rr;
    const float* ptg = g_pt2 + (size_t)m0 * Rr;

    float acc[8][8];
#pragma unroll
    for (int i = 0; i < 8; i++)
#pragma unroll
        for (int j = 0; j < 8; j++) acc[i][j] = 0.f;

    for (int c = 0; c < Rr; c += 16) {
#pragma unroll
        for (int t = 0; t < 2; t++) {
            int f = tid + 256 * t;
            int r = f >> 2, q = f & 3;
            float4 v = *(const float4*)&psg[(size_t)r * Rr + c + 4 * q];
            sps[(4 * q + 0) * 132 + r] = v.x;
            sps[(4 * q + 1) * 132 + r] = v.y;
            sps[(4 * q + 2) * 132 + r] = v.z;
            sps[(4 * q + 3) * 132 + r] = v.w;
            float4 u = *(const float4*)&ptg[(size_t)r * Rr + c + 4 * q];
            spt[(4 * q + 0) * 132 + r] = u.x;
            spt[(4 * q + 1) * 132 + r] = u.y;
            spt[(4 * q + 2) * 132 + r] = u.z;
            spt[(4 * q + 3) * 132 + r] = u.w;
        }
        __syncthreads();
#pragma unroll
        for (int kk = 0; kk < 16; kk++) {
            float4 a0 = *(const float4*)&sps[kk * 132 + sg];
            float4 a1 = *(const float4*)&sps[kk * 132 + sg + 4];
            float4 c0 = *(const float4*)&spt[kk * 132 + mg];
            float4 c1 = *(const float4*)&spt[kk * 132 + mg + 4];
            float sv[8] = {a0.x, a0.y, a0.z, a0.w, a1.x, a1.y, a1.z, a1.w};
            float mv[8] = {c0.x, c0.y, c0.z, c0.w, c1.x, c1.y, c1.z, c1.w};
#pragma unroll
            for (int i = 0; i < 8; i++)
#pragma unroll
                for (int j = 0; j < 8; j++)
                    acc[i][j] = fmaf(mv[i], sv[j], acc[i][j]);
        }
        __syncthreads();
    }
#pragma unroll
    for (int i = 0; i < 8; i++) {
        float* o = g_scores + ((size_t)(b * Mm + m0 + mg + i)) * Ss + s0 + sg;
        *(float4*)(o)     = make_float4(acc[i][0], acc[i][1], acc[i][2], acc[i][3]);
        *(float4*)(o + 4) = make_float4(acc[i][4], acc[i][5], acc[i][6], acc[i][7]);
    }
}

// ---------------- kernel: write phase (top-16 over S, edges, gather-add, LN) ----------------
// Per-warp tournament top-16 -> 128 candidates -> parallel bitonic sort (desc, idx-tiebreak)
__global__ __launch_bounds__(256) void write_kernel(
    const float* __restrict__ token_val, const float* __restrict__ token_state,
    const float* __restrict__ ln_g, const float* __restrict__ ln_b) {
    int bm = blockIdx.x;
    int b = bm >> 8, m = bm & 255;
    int tid = threadIdx.x, w = tid >> 5, lane = tid & 31;
    __shared__ unsigned long long s_keys[128];
    __shared__ float s_edge[16];
    __shared__ int s_eidx[16];
    __shared__ float swr[18];

    const float* row = g_scores + (size_t)bm * Ss;

    // per-warp top-16 of its 256-element chunk (extraction order: abs desc, idx asc)
    {
        int base = w * 256 + lane;
        float va[8];
#pragma unroll
        for (int j = 0; j < 8; j++) va[j] = fabsf(row[base + 32 * j]);
        for (int p = 0; p < 16; p++) {
            float best = -1.f;
            int bj = 0;
#pragma unroll
            for (int j = 0; j < 8; j++)
                if (va[j] > best) { best = va[j]; bj = j; }
            int bidx = base + 32 * bj;
#pragma unroll
            for (int off = 16; off; off >>= 1) {
                float ob = __shfl_down_sync(0xffffffffu, best, off);
                int oi = __shfl_down_sync(0xffffffffu, bidx, off);
                if (ob > best || (ob == best && oi < bidx)) { best = ob; bidx = oi; }
            }
            best = __shfl_sync(0xffffffffu, best, 0);
            bidx = __shfl_sync(0xffffffffu, bidx, 0);
#pragma unroll
            for (int j = 0; j < 8; j++)
                if (base + 32 * j == bidx) va[j] = -1.f;
            if (lane == 0)
                s_keys[w * 16 + p] =
                    ((unsigned long long)__float_as_uint(best) << 32) | (unsigned)(~bidx);
        }
    }
    __syncthreads();

    // bitonic sort 128 keys descending (key = abs_bits<<32 | ~idx => jax tie-break)
    for (int k = 2; k <= 128; k <<= 1) {
        for (int j = k >> 1; j; j >>= 1) {
            int i = tid, l = i ^ j;
            if (i < 128 && l > i) {
                unsigned long long a = s_keys[i], bq = s_keys[l];
                bool sw = ((i & k) == 0) ? (a < bq) : (a > bq);
                if (sw) { s_keys[i] = bq; s_keys[l] = a; }
            }
            __syncthreads();
        }
    }

    // edges + state update (warp 0, lanes 0..15). sorted[0] has max abs.
    if (w == 0) {
        bool valid = lane < 16;
        unsigned long long key = s_keys[valid ? lane : 0];
        float a = __uint_as_float((unsigned)(key >> 32));
        int idx = (int)(~(unsigned)key);
        float maxa = __shfl_sync(0xffffffffu, a, 0);
        float sel = valid ? row[idx] : 0.f;
        float e = valid ? expf(a - maxa) : 0.f;
        float sum = e;
#pragma unroll
        for (int off = 8; off; off >>= 1) sum += __shfl_xor_sync(0xffffffffu, sum, off, 16);
        float sgn = (sel > 0.f) ? 1.f : ((sel < 0.f) ? -1.f : 0.f);
        float edge = sgn * e / sum;
        if (valid) { s_edge[lane] = edge; s_eidx[lane] = idx; }
        float c = valid ? edge * token_state[(size_t)b * Ss + idx] : 0.f;
#pragma unroll
        for (int off = 8; off; off >>= 1) c += __shfl_xor_sync(0xffffffffu, c, off, 16);
        if (lane == 0) g_state1_raw[bm] = g_mem_state0[m] + c;
    }
    __syncthreads();

    // value update + LN
    int d = tid;
    float a0 = g_mem_val0[(size_t)m * Dd + d];
    float a1 = g_mem_val0[(size_t)m * Dd + d + 256];
#pragma unroll
    for (int k = 0; k < 16; k++) {
        const float* tv = token_val + ((size_t)b * Ss + s_eidx[k]) * Dd;
        float ek = s_edge[k];
        a0 = fmaf(ek, tv[d], a0);
        a1 = fmaf(ek, tv[d + 256], a1);
    }
    float mu, ri;
    block_ln_512(a0, a1, mu, ri, swr);
    float* o = g_mem_val1 + (size_t)bm * Dd;
    o[d]       = (a0 - mu) * ri * ln_g[d] + ln_b[d];
    o[d + 256] = (a1 - mu) * ri * ln_g[d + 256] + ln_b[d + 256];
}

// ---------------- kernel: propagation, 8 slot-rows per block ----------------
// grid 512: b = blk>>5, i0 = (blk&31)*8. Stages qs2[b] once; 8 parallel bitonic top-16.
__global__ __launch_bounds__(256) void prop8_kernel(
    float* __restrict__ out_final, const float* __restrict__ ln_g,
    const float* __restrict__ ln_b) {
    int b = blockIdx.x >> 5;
    int i0 = (blockIdx.x & 31) * 8;
    int tid = threadIdx.x, w = tid >> 5, lane = tid & 31;
    __shared__ float s_qt[8][68];
    __shared__ float sqs[32][68];
    __shared__ float prow[8][256];
    __shared__ unsigned long long keys8[8][256];
    __shared__ float s_edge[8][16];
    __shared__ int s_eidx[8][16];
    __shared__ float swr[18];

    // stage qt rows for the 8 target slots
    {
        int f = tid;  // 8 rows x 16 quads = 128 float4
        if (f < 128) {
            int r = f >> 4, q = f & 15;
            *(float4*)&s_qt[r][q * 4] =
                *(const float4*)&g_qt[((size_t)(b * Mm + i0 + r)) * Rr + 4 * q];
        }
    }
    __syncthreads();

    // pscores: prow[r][j] = dot(qt[r], qs2[b][j])  (state weight folded into qs2)
    int rg = tid >> 5;   // warp = r
    for (int j0 = 0; j0 < Mm; j0 += 32) {
#pragma unroll
        for (int t = 0; t < 2; t++) {
            int f = tid + 256 * t;
            int jj = f >> 4, q = f & 15;
            *(float4*)&sqs[jj][q * 4] =
                *(const float4*)&g_qs2[((size_t)(b * Mm + j0 + jj)) * Rr + 4 * q];
        }
        __syncthreads();
        float acc = 0.f;
#pragma unroll
        for (int k4 = 0; k4 < Rr; k4 += 4) {
            float4 qv = *(const float4*)&sqs[lane][k4];
            float4 tv = *(const float4*)&s_qt[rg][k4];
            acc = fmaf(qv.x, tv.x, fmaf(qv.y, tv.y, fmaf(qv.z, tv.z, fmaf(qv.w, tv.w, acc))));
        }
        prow[rg][j0 + lane] = acc;
        __syncthreads();
    }

    // build keys: 8 rows x 256 elements
#pragma unroll
    for (int r = 0; r < 8; r++) {
        float v = prow[r][tid];
        keys8[r][tid] =
            ((unsigned long long)__float_as_uint(fabsf(v)) << 32) | (unsigned)(~tid);
    }
    __syncthreads();

    // 8 parallel bitonic sorts of 256 keys, descending
    for (int k = 2; k <= 256; k <<= 1) {
        for (int j = k >> 1; j; j >>= 1) {
            int i = tid, l = i ^ j;
            if (l > i) {
                bool up = ((i & k) == 0);
#pragma unroll
                for (int r = 0; r < 8; r++) {
                    unsigned long long a = keys8[r][i], bq = keys8[r][l];
                    bool sw = up ? (a < bq) : (a > bq);
                    if (sw) { keys8[r][i] = bq; keys8[r][l] = a; }
                }
            }
            __syncthreads();
        }
    }

    // edges: warp r handles row r (lanes 0..15)
    {
        int r = w;
        bool valid = lane < 16;
        unsigned long long key = keys8[r][valid ? lane : 0];
        float a = __uint_as_float((unsigned)(key >> 32));
        int idx = (int)(~(unsigned)key);
        float maxa = __shfl_sync(0xffffffffu, a, 0);
        float sel = valid ? prow[r][idx] : 0.f;
        float e = valid ? expf(a - maxa) : 0.f;
        float sum = e;
#pragma unroll
        for (int off = 8; off; off >>= 1) sum += __shfl_xor_sync(0xffffffffu, sum, off, 16);
        float sgn = (sel > 0.f) ? 1.f : ((sel < 0.f) ? -1.f : 0.f);
        float edge = sgn * e / sum;
        if (valid) { s_edge[r][lane] = edge; s_eidx[r][lane] = idx; }
    }
    __syncthreads();

    // residual gather + final LN, row by row (whole block per row)
    for (int r = 0; r < 8; r++) {
        int bi = b * Mm + i0 + r;
        int d = tid;
        float a0 = g_mem_val1[(size_t)bi * Dd + d];
        float a1 = g_mem_val1[(size_t)bi * Dd + d + 256];
#pragma unroll
        for (int k = 0; k < 16; k++) {
            const float* mv = g_mem_val1 + ((size_t)(b * Mm + s_eidx[r][k])) * Dd;
            float ek = s_edge[r][k];
            a0 = fmaf(ek, mv[d], a0);
            a1 = fmaf(ek, mv[d + 256], a1);
        }
        float mu, ri;
        block_ln_512(a0, a1, mu, ri, swr);
        float* o = out_final + (size_t)bi * Dd;
        o[d]       = (a0 - mu) * ri * ln_g[d] + ln_b[d];
        o[d + 256] = (a1 - mu) * ri * ln_g[d + 256] + ln_b[d + 256];
        __syncthreads();
    }
}

// ---------------- host launch ----------------
extern "C" void kernel_launch(void* const* d_in, const int* in_sizes, int n_in,
                              void* d_out, int out_size) {
    (void)in_sizes; (void)n_in; (void)out_size;
    const float* token_val   = (const float*)d_in[0];
    const float* token_state = (const float*)d_in[1];
    const float* init_state  = (const float*)d_in[2];
    const float* init_val    = (const float*)d_in[3];
    const float* rUs_w = (const float*)d_in[4];
    const float* rUs_b = (const float*)d_in[5];
    const float* rUt_w = (const float*)d_in[6];
    const float* rUt_b = (const float*)d_in[7];
    const float* r_w   = (const float*)d_in[8];
    const float* pUs_w = (const float*)d_in[9];
    const float* pUs_b = (const float*)d_in[10];
    const float* pUt_w = (const float*)d_in[11];
    const float* pUt_b = (const float*)d_in[12];
    const float* p_w   = (const float*)d_in[13];
    const float* ln_g  = (const float*)d_in[14];
    const float* ln_b  = (const float*)d_in[15];
    float* out = (float*)d_out;

    float *p_mv0, *p_pt2, *p_ps, *p_mv1, *p_qt, *p_qs2, *p_st0, *p_st1raw, *p_st1;
    cudaGetSymbolAddress((void**)&p_mv0, g_mem_val0);
    cudaGetSymbolAddress((void**)&p_pt2, g_pt2);
    cudaGetSymbolAddress((void**)&p_ps, g_ps);
    cudaGetSymbolAddress((void**)&p_mv1, g_mem_val1);
    cudaGetSymbolAddress((void**)&p_qt, g_qt);
    cudaGetSymbolAddress((void**)&p_qs2, g_qs2);
    cudaGetSymbolAddress((void**)&p_st0, g_mem_state0);
    cudaGetSymbolAddress((void**)&p_st1raw, g_state1_raw);
    cudaGetSymbolAddress((void**)&p_st1, g_state1);

    // mem_val0 = LN(init_val)  (batch independent)
    ln_rows_kernel<<<Mm, 256>>>(init_val, p_mv0, ln_g, ln_b);
    // mem_state0 = signed_softmax_state(init_state)
    sss_kernel<<<1, 256>>>(init_state, p_st0);
    // combined: blocks [0,256) -> ps = token_val @ rUs + b ; blocks [256,258) -> pt2
    gemm_proj<128><<<258, 256>>>(256,
        token_val, p_ps, rUs_w, rUs_b, nullptr, nullptr,
        p_mv0, p_pt2, rUt_w, rUt_b, r_w, nullptr);
    // scores = pt2 . ps
    scores2_kernel<<<dim3(Ss / 128, Mm / 128, Bb), 256>>>();
    // write phase: topk (bitonic merge) + edges + gather-add + LN; raw state update
    write_kernel<<<Bb * Mm, 256>>>(token_val, token_state, ln_g, ln_b);
    // state1 = signed_softmax_state(state1_raw)
    sss_kernel<<<Bb, 256>>>(p_st1raw, p_st1);
    // fused: y=0 -> qt = (mem_val1 @ pUt + b)*p_w*0.1 ; y=1 -> qs2 = (mem_val1 @ pUs + b)*state1
    gemm_proj<32><<<dim3((Bb * Mm) / 32, 2), 256>>>(-1,
        p_mv1, p_qt, pUt_w, pUt_b, p_w, nullptr,
        p_mv1, p_qs2, pUs_w, pUs_b, nullptr, p_st1);
    // propagation (8 rows/block) + final LN -> out
    prop8_kernel<<<(Bb * Mm) / 8, 256>>>(out, ln_g, ln_b);
}

// round 5
// speedup vs baseline: 2.1669x; 1.3595x over previous
#include <cuda_runtime.h>
#include <math.h>
#include <stdint.h>

// Problem shapes (fixed by the dataset)
constexpr int Bb = 16;    // batch
constexpr int Ss = 2048;  // tokens
constexpr int Dd = 512;   // dim
constexpr int Mm = 256;   // memory slots
constexpr int Rr = 64;    // low rank
constexpr float EPS = 1e-5f;
constexpr float STATE_MASS = 4.0f;
constexpr float LRS = 0.1f;

typedef unsigned long long ull;

// ---------------- scratch (static device globals; no allocs) ----------------
__device__ float g_scores[(size_t)Bb * Mm * Ss];   // 33.5 MB (L2-resident) [b][m][s]
__device__ float g_ps[(size_t)Bb * Ss * Rr];       // 8.4 MB   [b*S+s][r]
__device__ float g_mem_val0[(size_t)Mm * Dd];      // LN(init_val), batch-independent
__device__ float g_pt2[(size_t)Mm * Rr];           // (mem_val0@rUt + b) * r_w * 0.1
__device__ float g_mem_state0[Mm];                 // signed-softmax-state(init_state)
__device__ float g_mem_val1[(size_t)Bb * Mm * Dd]; // post-write, post-LN
__device__ float g_state1_raw[(size_t)Bb * Mm];
__device__ float g_state1[(size_t)Bb * Mm];
__device__ float g_qt[(size_t)Bb * Mm * Rr];       // (mem_val1@pUt + b) * p_w * 0.1
__device__ float g_qs2[(size_t)Bb * Mm * Rr];      // (mem_val1@pUs + b) * state1[b,j]

// ---------------- shared helpers ----------------
__device__ __forceinline__ void block_ln_512(float a0, float a1, float& mu, float& ri,
                                             float* swr) {
    float ps = a0 + a1;
    float pq = fmaf(a0, a0, a1 * a1);
#pragma unroll
    for (int off = 16; off; off >>= 1) {
        ps += __shfl_down_sync(0xffffffffu, ps, off);
        pq += __shfl_down_sync(0xffffffffu, pq, off);
    }
    int tid = threadIdx.x, wid = tid >> 5, lane = tid & 31;
    if (lane == 0) { swr[wid] = ps; swr[8 + wid] = pq; }
    __syncthreads();
    if (tid == 0) {
        float s = 0.f, q = 0.f;
#pragma unroll
        for (int i = 0; i < 8; i++) { s += swr[i]; q += swr[8 + i]; }
        float m = s * (1.0f / 512.0f);
        float v = q * (1.0f / 512.0f) - m * m;
        swr[16] = m;
        swr[17] = rsqrtf(v + EPS);
    }
    __syncthreads();
    mu = swr[16];
    ri = swr[17];
}

// ---------------- kernel: LayerNorm rows (row length 512) ----------------
__global__ void ln_rows_kernel(const float* __restrict__ in, float* __restrict__ out,
                               const float* __restrict__ g, const float* __restrict__ bta) {
    __shared__ float swr[18];
    int row = blockIdx.x, tid = threadIdx.x;
    const float* x = in + (size_t)row * Dd;
    float a0 = x[tid], a1 = x[tid + 256];
    float mu, ri;
    block_ln_512(a0, a1, mu, ri, swr);
    float* o = out + (size_t)row * Dd;
    o[tid]       = (a0 - mu) * ri * g[tid] + bta[tid];
    o[tid + 256] = (a1 - mu) * ri * g[tid + 256] + bta[tid + 256];
}

// ---------------- kernel: signed softmax state over 256 slots ----------------
__global__ void sss_kernel(const float* __restrict__ in, float* __restrict__ out) {
    int tid = threadIdx.x;
    const float* x = in + (size_t)blockIdx.x * Mm;
    float v = x[tid];
    float a = fabsf(v);
    __shared__ float swr[8];
    __shared__ float s_bc[2];
    int wid = tid >> 5, lane = tid & 31;
    float m = a;
#pragma unroll
    for (int off = 16; off; off >>= 1) m = fmaxf(m, __shfl_down_sync(0xffffffffu, m, off));
    if (lane == 0) swr[wid] = m;
    __syncthreads();
    if (tid == 0) {
        float mm = swr[0];
#pragma unroll
        for (int i = 1; i < 8; i++) mm = fmaxf(mm, swr[i]);
        s_bc[0] = mm;
    }
    __syncthreads();
    float e = expf(a - s_bc[0]);
    float s = e;
#pragma unroll
    for (int off = 16; off; off >>= 1) s += __shfl_down_sync(0xffffffffu, s, off);
    __syncthreads();
    if (lane == 0) swr[wid] = s;
    __syncthreads();
    if (tid == 0) {
        float ss = 0.f;
#pragma unroll
        for (int i = 0; i < 8; i++) ss += swr[i];
        s_bc[1] = ss;
    }
    __syncthreads();
    float sgn = (v > 0.f) ? 1.f : ((v < 0.f) ? -1.f : 0.f);
    out[(size_t)blockIdx.x * Mm + tid] = sgn * e / s_bc[1] * STATE_MASS;
}

// ---------------- tiled projection GEMM: out[rows,64] = X[rows,512] @ W[512,64] ----------------
template <int RT>
__global__ __launch_bounds__(256) void gemm_proj(
    int split,
    const float* __restrict__ X0,
    float* __restrict__ out0, const float* __restrict__ W0, const float* __restrict__ b0,
    const float* __restrict__ rs0, const float* __restrict__ rowsc0,
    const float* __restrict__ X1,
    float* __restrict__ out1, const float* __restrict__ W1, const float* __restrict__ b1,
    const float* __restrict__ rs1, const float* __restrict__ rowsc1) {
    constexpr int RPT = RT / 16;
    constexpr int XSTR = RT + 4;
    __shared__ float sx[16 * XSTR];
    __shared__ float sw[16 * 68];

    int tid = threadIdx.x;
    int set, rowblk;
    if (split >= 0) {
        set = ((int)blockIdx.x >= split);
        rowblk = set ? (int)blockIdx.x - split : (int)blockIdx.x;
    } else {
        set = blockIdx.y;
        rowblk = blockIdx.x;
    }
    int row0 = rowblk * RT;
    const float* X     = set ? X1 : X0;
    const float* W     = set ? W1 : W0;
    const float* bias  = set ? b1 : b0;
    const float* rs    = set ? rs1 : rs0;
    const float* rowsc = set ? rowsc1 : rowsc0;
    float* out         = set ? out1 : out0;

    int rowg = tid >> 4;
    int colg = tid & 15;

    float acc[RPT][4];
#pragma unroll
    for (int r = 0; r < RPT; r++)
#pragma unroll
        for (int c = 0; c < 4; c++) acc[r][c] = 0.f;

    for (int k0 = 0; k0 < Dd; k0 += 16) {
        constexpr int NV = RT * 16 / 4;
#pragma unroll
        for (int t = 0; t < (NV + 255) / 256; t++) {
            int f = tid + 256 * t;
            if ((NV % 256 == 0) || (f < NV)) {
                int row = f >> 2, q = f & 3;
                float4 v = *(const float4*)&X[(size_t)(row0 + row) * Dd + k0 + 4 * q];
                sx[(4 * q + 0) * XSTR + row] = v.x;
                sx[(4 * q + 1) * XSTR + row] = v.y;
                sx[(4 * q + 2) * XSTR + row] = v.z;
                sx[(4 * q + 3) * XSTR + row] = v.w;
            }
        }
        {
            int k = tid >> 4, c = tid & 15;
            float4 v = *(const float4*)&W[(size_t)(k0 + k) * Rr + 4 * c];
            *(float4*)&sw[k * 68 + 4 * c] = v;
        }
        __syncthreads();
#pragma unroll
        for (int kk = 0; kk < 16; kk++) {
            float4 wv = *(const float4*)&sw[kk * 68 + colg * 4];
            float xr[RPT];
            if constexpr (RPT == 8) {
                float4 x0 = *(const float4*)&sx[kk * XSTR + rowg * 8];
                float4 x1 = *(const float4*)&sx[kk * XSTR + rowg * 8 + 4];
                xr[0] = x0.x; xr[1] = x0.y; xr[2] = x0.z; xr[3] = x0.w;
                xr[4] = x1.x; xr[5] = x1.y; xr[6] = x1.z; xr[7] = x1.w;
            } else {
                float2 x0 = *(const float2*)&sx[kk * XSTR + rowg * RPT];
                xr[0] = x0.x; xr[1] = x0.y;
            }
#pragma unroll
            for (int r = 0; r < RPT; r++) {
                acc[r][0] = fmaf(xr[r], wv.x, acc[r][0]);
                acc[r][1] = fmaf(xr[r], wv.y, acc[r][1]);
                acc[r][2] = fmaf(xr[r], wv.z, acc[r][2]);
                acc[r][3] = fmaf(xr[r], wv.w, acc[r][3]);
            }
        }
        __syncthreads();
    }

    float4 bv = *(const float4*)&bias[colg * 4];
    float s0 = 1.f, s1 = 1.f, s2 = 1.f, s3 = 1.f;
    if (rs) {
        float4 rv = *(const float4*)&rs[colg * 4];
        s0 = rv.x * LRS; s1 = rv.y * LRS; s2 = rv.z * LRS; s3 = rv.w * LRS;
    }
#pragma unroll
    for (int r = 0; r < RPT; r++) {
        int row = row0 + rowg * RPT + r;
        float rsc = rowsc ? rowsc[row] : 1.f;
        float4 o;
        o.x = (acc[r][0] + bv.x) * s0 * rsc;
        o.y = (acc[r][1] + bv.y) * s1 * rsc;
        o.z = (acc[r][2] + bv.z) * s2 * rsc;
        o.w = (acc[r][3] + bv.w) * s3 * rsc;
        *(float4*)&out[(size_t)row * Rr + colg * 4] = o;
    }
}

// ---------------- tiled scores GEMM ----------------
__global__ __launch_bounds__(256) void scores2_kernel() {
    __shared__ float sps[16 * 132];
    __shared__ float spt[16 * 132];
    int b = blockIdx.z;
    int s0 = blockIdx.x * 128;
    int m0 = blockIdx.y * 128;
    int tid = threadIdx.x;
    int sg = (tid & 15) * 8;
    int mg = (tid >> 4) * 8;

    const float* psg = g_ps + ((size_t)b * Ss + s0) * Rr;
    const float* ptg = g_pt2 + (size_t)m0 * Rr;

    float acc[8][8];
#pragma unroll
    for (int i = 0; i < 8; i++)
#pragma unroll
        for (int j = 0; j < 8; j++) acc[i][j] = 0.f;

    for (int c = 0; c < Rr; c += 16) {
#pragma unroll
        for (int t = 0; t < 2; t++) {
            int f = tid + 256 * t;
            int r = f >> 2, q = f & 3;
            float4 v = *(const float4*)&psg[(size_t)r * Rr + c + 4 * q];
            sps[(4 * q + 0) * 132 + r] = v.x;
            sps[(4 * q + 1) * 132 + r] = v.y;
            sps[(4 * q + 2) * 132 + r] = v.z;
            sps[(4 * q + 3) * 132 + r] = v.w;
            float4 u = *(const float4*)&ptg[(size_t)r * Rr + c + 4 * q];
            spt[(4 * q + 0) * 132 + r] = u.x;
            spt[(4 * q + 1) * 132 + r] = u.y;
            spt[(4 * q + 2) * 132 + r] = u.z;
            spt[(4 * q + 3) * 132 + r] = u.w;
        }
        __syncthreads();
#pragma unroll
        for (int kk = 0; kk < 16; kk++) {
            float4 a0 = *(const float4*)&sps[kk * 132 + sg];
            float4 a1 = *(const float4*)&sps[kk * 132 + sg + 4];
            float4 c0 = *(const float4*)&spt[kk * 132 + mg];
            float4 c1 = *(const float4*)&spt[kk * 132 + mg + 4];
            float sv[8] = {a0.x, a0.y, a0.z, a0.w, a1.x, a1.y, a1.z, a1.w};
            float mv[8] = {c0.x, c0.y, c0.z, c0.w, c1.x, c1.y, c1.z, c1.w};
#pragma unroll
            for (int i = 0; i < 8; i++)
#pragma unroll
                for (int j = 0; j < 8; j++)
                    acc[i][j] = fmaf(mv[i], sv[j], acc[i][j]);
        }
        __syncthreads();
    }
#pragma unroll
    for (int i = 0; i < 8; i++) {
        float* o = g_scores + ((size_t)(b * Mm + m0 + mg + i)) * Ss + s0 + sg;
        *(float4*)(o)     = make_float4(acc[i][0], acc[i][1], acc[i][2], acc[i][3]);
        *(float4*)(o + 4) = make_float4(acc[i][4], acc[i][5], acc[i][6], acc[i][7]);
    }
}

// ---------------- write phase: count-bisection top-16 + edges + gather + LN ----------------
__global__ __launch_bounds__(256) void write_kernel(
    const float* __restrict__ token_val, const float* __restrict__ token_state,
    const float* __restrict__ ln_g, const float* __restrict__ ln_b) {
    int bm = blockIdx.x;
    int b = bm >> 8, m = bm & 255;
    int tid = threadIdx.x, w = tid >> 5, lane = tid & 31;
    __shared__ ull skeys[64];
    __shared__ float swr[18];
    __shared__ int s_ic[8];
    __shared__ int s_tot;
    __shared__ float s_edge[16];
    __shared__ int s_eidx[16];

    const float* row = g_scores + (size_t)bm * Ss;

    // load 8 values/thread (coalesced)
    float aa[8];
#pragma unroll
    for (int j = 0; j < 8; j++) aa[j] = fabsf(row[tid + 256 * j]);

    // block max of |v|
    {
        unsigned um = 0;
#pragma unroll
        for (int j = 0; j < 8; j++) um = max(um, __float_as_uint(aa[j]));
        um = __reduce_max_sync(0xffffffffu, um);
        if (lane == 0) s_ic[w] = (int)um;
        __syncthreads();
        if (tid == 0) {
            unsigned mm = (unsigned)s_ic[0];
#pragma unroll
            for (int i = 1; i < 8; i++) mm = max(mm, (unsigned)s_ic[i]);
            swr[16] = __uint_as_float(mm);
        }
        __syncthreads();
    }
    float hi = swr[16], lo = 0.f;
    int cl = Ss;

    // bisection: find lo with 16 <= count(|v| > lo) <= 64
    for (int it = 0; it < 32 && cl > 64; it++) {
        float mid = 0.5f * (lo + hi);
        int c = 0;
#pragma unroll
        for (int j = 0; j < 8; j++) c += (aa[j] > mid);
        c = (int)__reduce_add_sync(0xffffffffu, (unsigned)c);
        if (lane == 0) s_ic[w] = c;
        __syncthreads();
        if (tid == 0) {
            int t = 0;
#pragma unroll
            for (int i = 0; i < 8; i++) t += s_ic[i];
            s_tot = t;
        }
        __syncthreads();
        int tot = s_tot;
        if (tot >= 16) { lo = mid; cl = tot; } else { hi = mid; }
        __syncthreads();
    }

    // compact survivors (<= 64) into skeys
    if (tid == 0) s_tot = 0;
    if (tid < 64) skeys[tid] = 0ull;
    __syncthreads();
#pragma unroll
    for (int j = 0; j < 8; j++) {
        if (aa[j] > lo) {
            int p = atomicAdd(&s_tot, 1);
            if (p < 64)
                skeys[p] = ((ull)__float_as_uint(aa[j]) << 32) | (unsigned)(~(tid + 256 * j));
        }
    }
    __syncthreads();

    // bitonic sort 64 keys descending (key = abs<<32 | ~idx => jax tie-break)
    for (int k = 2; k <= 64; k <<= 1) {
        for (int j = k >> 1; j; j >>= 1) {
            int i = tid, l = i ^ j;
            if (i < 64 && l > i) {
                ull a = skeys[i], bq = skeys[l];
                bool sw2 = ((i & k) == 0) ? (a < bq) : (a > bq);
                if (sw2) { skeys[i] = bq; skeys[l] = a; }
            }
            __syncthreads();
        }
    }

    // edges + state update (warp 0, lanes 0..15)
    if (w == 0) {
        bool valid = lane < 16;
        ull key = skeys[valid ? lane : 0];
        float a = __uint_as_float((unsigned)(key >> 32));
        int idx = (int)(~(unsigned)key);
        float maxa = __shfl_sync(0xffffffffu, a, 0);
        float sel = valid ? row[idx] : 0.f;
        float e = valid ? expf(a - maxa) : 0.f;
        float sum = e;
#pragma unroll
        for (int off = 8; off; off >>= 1) sum += __shfl_xor_sync(0xffffffffu, sum, off, 16);
        float sgn = (sel > 0.f) ? 1.f : ((sel < 0.f) ? -1.f : 0.f);
        float edge = sgn * e / sum;
        if (valid) { s_edge[lane] = edge; s_eidx[lane] = idx; }
        float c = valid ? edge * token_state[(size_t)b * Ss + idx] : 0.f;
#pragma unroll
        for (int off = 8; off; off >>= 1) c += __shfl_xor_sync(0xffffffffu, c, off, 16);
        if (lane == 0) g_state1_raw[bm] = g_mem_state0[m] + c;
    }
    __syncthreads();

    // value update + LN
    int d = tid;
    float a0 = g_mem_val0[(size_t)m * Dd + d];
    float a1 = g_mem_val0[(size_t)m * Dd + d + 256];
#pragma unroll
    for (int k = 0; k < 16; k++) {
        const float* tv = token_val + ((size_t)b * Ss + s_eidx[k]) * Dd;
        float ek = s_edge[k];
        a0 = fmaf(ek, tv[d], a0);
        a1 = fmaf(ek, tv[d + 256], a1);
    }
    float mu, ri;
    block_ln_512(a0, a1, mu, ri, swr);
    float* o = g_mem_val1 + (size_t)bm * Dd;
    o[d]       = (a0 - mu) * ri * ln_g[d] + ln_b[d];
    o[d + 256] = (a1 - mu) * ri * ln_g[d + 256] + ln_b[d + 256];
}

// ---------------- propagation: 8 rows/block, per-warp bisection top-16 ----------------
__global__ __launch_bounds__(256) void prop8_kernel(
    float* __restrict__ out_final, const float* __restrict__ ln_g,
    const float* __restrict__ ln_b) {
    int b = blockIdx.x >> 5;
    int i0 = (blockIdx.x & 31) * 8;
    int tid = threadIdx.x, w = tid >> 5, lane = tid & 31;
    __shared__ float s_qt[8][68];
    __shared__ float sqs[32][68];
    __shared__ float prow[8][256];
    __shared__ ull wkeys[8][32];
    __shared__ float s_edge[8][16];
    __shared__ int s_eidx[8][16];
    __shared__ float swr[18];

    // stage qt rows for the 8 target slots
    if (tid < 128) {
        int r = tid >> 4, q = tid & 15;
        *(float4*)&s_qt[r][q * 4] =
            *(const float4*)&g_qt[((size_t)(b * Mm + i0 + r)) * Rr + 4 * q];
    }
    __syncthreads();

    // pscores: prow[w][j] = dot(qt[w], qs2[b][j]); element j = r*32+lane kept in regs
    float pv[8];
    for (int j0 = 0; j0 < Mm; j0 += 32) {
#pragma unroll
        for (int t = 0; t < 2; t++) {
            int f = tid + 256 * t;
            int jj = f >> 4, q = f & 15;
            *(float4*)&sqs[jj][q * 4] =
                *(const float4*)&g_qs2[((size_t)(b * Mm + j0 + jj)) * Rr + 4 * q];
        }
        __syncthreads();
        float acc = 0.f;
#pragma unroll
        for (int k4 = 0; k4 < Rr; k4 += 4) {
            float4 qv = *(const float4*)&sqs[lane][k4];
            float4 tv = *(const float4*)&s_qt[w][k4];
            acc = fmaf(qv.x, tv.x, fmaf(qv.y, tv.y, fmaf(qv.z, tv.z, fmaf(qv.w, tv.w, acc))));
        }
        pv[j0 >> 5] = acc;
        prow[w][j0 + lane] = acc;
        __syncthreads();
    }

    // per-warp top-16 of 256 via count-bisection (no block syncs)
    float av[8];
#pragma unroll
    for (int r = 0; r < 8; r++) av[r] = fabsf(pv[r]);
    unsigned um = 0;
#pragma unroll
    for (int r = 0; r < 8; r++) um = max(um, __float_as_uint(av[r]));
    um = __reduce_max_sync(0xffffffffu, um);
    float hi = __uint_as_float(um), lo = 0.f;
    int cl = 256;
    for (int it = 0; it < 32 && cl > 32; it++) {
        float mid = 0.5f * (lo + hi);
        int c = 0;
#pragma unroll
        for (int r = 0; r < 8; r++) c += (av[r] > mid);
        c = (int)__reduce_add_sync(0xffffffffu, (unsigned)c);
        if (c >= 16) { lo = mid; cl = c; } else { hi = mid; }
    }

    // ballot-compact survivors (<=32) into wkeys[w]
    wkeys[w][lane] = 0ull;
    __syncwarp();
    int base = 0;
#pragma unroll
    for (int r = 0; r < 8; r++) {
        bool p = av[r] > lo;
        unsigned msk = __ballot_sync(0xffffffffu, p);
        if (p) {
            int pos = base + __popc(msk & ((1u << lane) - 1));
            if (pos < 32)
                wkeys[w][pos] =
                    ((ull)__float_as_uint(av[r]) << 32) | (unsigned)(~(r * 32 + lane));
        }
        base += __popc(msk);
    }
    __syncwarp();

    // warp bitonic sort of 32 keys (descending)
    ull key = wkeys[w][lane];
#pragma unroll
    for (int k = 2; k <= 32; k <<= 1) {
#pragma unroll
        for (int j = k >> 1; j; j >>= 1) {
            ull other = __shfl_xor_sync(0xffffffffu, key, j);
            bool dirDesc = ((lane & k) == 0);
            bool upper = (lane & j) != 0;
            bool takeMax = (dirDesc != upper);
            ull mx2 = key > other ? key : other;
            ull mn2 = key > other ? other : key;
            key = takeMax ? mx2 : mn2;
        }
    }

    // edges for row w (lanes 0..15)
    {
        bool valid = lane < 16;
        float a = __uint_as_float((unsigned)(key >> 32));
        int idx = (int)(~(unsigned)key);
        float maxa = __shfl_sync(0xffffffffu, a, 0);
        float sel = valid ? prow[w][idx] : 0.f;
        float e = valid ? expf(a - maxa) : 0.f;
        float sum = e;
#pragma unroll
        for (int off = 8; off; off >>= 1) sum += __shfl_xor_sync(0xffffffffu, sum, off, 16);
        float sgn = (sel > 0.f) ? 1.f : ((sel < 0.f) ? -1.f : 0.f);
        float edge = sgn * e / sum;
        if (valid) { s_edge[w][lane] = edge; s_eidx[w][lane] = idx; }
    }
    __syncthreads();

    // residual gather + final LN, row by row
    for (int r = 0; r < 8; r++) {
        int bi = b * Mm + i0 + r;
        int d = tid;
        float a0 = g_mem_val1[(size_t)bi * Dd + d];
        float a1 = g_mem_val1[(size_t)bi * Dd + d + 256];
#pragma unroll
        for (int k = 0; k < 16; k++) {
            const float* mv = g_mem_val1 + ((size_t)(b * Mm + s_eidx[r][k])) * Dd;
            float ek = s_edge[r][k];
            a0 = fmaf(ek, mv[d], a0);
            a1 = fmaf(ek, mv[d + 256], a1);
        }
        float mu, ri;
        block_ln_512(a0, a1, mu, ri, swr);
        float* o = out_final + (size_t)bi * Dd;
        o[d]       = (a0 - mu) * ri * ln_g[d] + ln_b[d];
        o[d + 256] = (a1 - mu) * ri * ln_g[d + 256] + ln_b[d + 256];
        __syncthreads();
    }
}

// ---------------- host launch ----------------
extern "C" void kernel_launch(void* const* d_in, const int* in_sizes, int n_in,
                              void* d_out, int out_size) {
    (void)in_sizes; (void)n_in; (void)out_size;
    const float* token_val   = (const float*)d_in[0];
    const float* token_state = (const float*)d_in[1];
    const float* init_state  = (const float*)d_in[2];
    const float* init_val    = (const float*)d_in[3];
    const float* rUs_w = (const float*)d_in[4];
    const float* rUs_b = (const float*)d_in[5];
    const float* rUt_w = (const float*)d_in[6];
    const float* rUt_b = (const float*)d_in[7];
    const float* r_w   = (const float*)d_in[8];
    const float* pUs_w = (const float*)d_in[9];
    const float* pUs_b = (const float*)d_in[10];
    const float* pUt_w = (const float*)d_in[11];
    const float* pUt_b = (const float*)d_in[12];
    const float* p_w   = (const float*)d_in[13];
    const float* ln_g  = (const float*)d_in[14];
    const float* ln_b  = (const float*)d_in[15];
    float* out = (float*)d_out;

    float *p_mv0, *p_pt2, *p_ps, *p_mv1, *p_qt, *p_qs2, *p_st0, *p_st1raw, *p_st1;
    cudaGetSymbolAddress((void**)&p_mv0, g_mem_val0);
    cudaGetSymbolAddress((void**)&p_pt2, g_pt2);
    cudaGetSymbolAddress((void**)&p_ps, g_ps);
    cudaGetSymbolAddress((void**)&p_mv1, g_mem_val1);
    cudaGetSymbolAddress((void**)&p_qt, g_qt);
    cudaGetSymbolAddress((void**)&p_qs2, g_qs2);
    cudaGetSymbolAddress((void**)&p_st0, g_mem_state0);
    cudaGetSymbolAddress((void**)&p_st1raw, g_state1_raw);
    cudaGetSymbolAddress((void**)&p_st1, g_state1);

    // mem_val0 = LN(init_val); mem_state0 = sss(init_state)
    ln_rows_kernel<<<Mm, 256>>>(init_val, p_mv0, ln_g, ln_b);
    sss_kernel<<<1, 256>>>(init_state, p_st0);
    // combined: blocks [0,256) -> ps ; blocks [256,258) -> pt2
    gemm_proj<128><<<258, 256>>>(256,
        token_val, p_ps, rUs_w, rUs_b, nullptr, nullptr,
        p_mv0, p_pt2, rUt_w, rUt_b, r_w, nullptr);
    // scores = pt2 . ps
    scores2_kernel<<<dim3(Ss / 128, Mm / 128, Bb), 256>>>();
    // write phase: bisection topk + edges + gather-add + LN; raw state update
    write_kernel<<<Bb * Mm, 256>>>(token_val, token_state, ln_g, ln_b);
    // state1 = signed_softmax_state(state1_raw)
    sss_kernel<<<Bb, 256>>>(p_st1raw, p_st1);
    // fused: y=0 -> qt ; y=1 -> qs2 (state folded into rows)
    gemm_proj<32><<<dim3((Bb * Mm) / 32, 2), 256>>>(-1,
        p_mv1, p_qt, pUt_w, pUt_b, p_w, nullptr,
        p_mv1, p_qs2, pUs_w, pUs_b, nullptr, p_st1);
    // propagation (8 rows/block, warp bisection) + final LN -> out
    prop8_kernel<<<(Bb * Mm) / 8, 256>>>(out, ln_g, ln_b);
}